// round 4
// baseline (speedup 1.0000x reference)
#include <cuda_runtime.h>
#include <cuda_bf16.h>
#include <stdint.h>

// Problem constants
#define N_TOK   2048
#define DIM     512
#define HOUT    512
#define NEXP    16

#define BM 64
#define BN 64
#define BK 16
// worst-case padded tiles: floor(2048/64) + 16 = 48
#define MAX_TILES 48
#define PAD_TOK   (MAX_TILES * BM)

// Scratch (no allocations allowed)
__device__ int g_order[PAD_TOK];         // token id per padded slot, -1 = pad
__device__ int g_tile_expert[MAX_TILES]; // expert id per m-tile, -1 = unused

// ---------------------------------------------------------------------------
// Pass 1: bucket tokens by expert, build padded order + tile map.
// Single block, 256 threads.
// The idx tensor is declared int64 in the reference, but JAX's default
// x64-disable typically dumps it as int32. Detect the element stride:
// for true int64 (values 0..15, little-endian) every odd 32-bit word is 0;
// for int32 random values that's impossible (P ~ 16^-1024).
// ---------------------------------------------------------------------------
__global__ void bucket_kernel(const int* __restrict__ idx32, int n)
{
    __shared__ int cnt[NEXP];
    __shared__ int off[NEXP];
    __shared__ int cur[NEXP];
    __shared__ int odd_or;
    const int t = threadIdx.x;

    if (t == 0) odd_or = 0;
    if (t < NEXP) cnt[t] = 0;
    __syncthreads();

    // OR-reduce the odd 32-bit words of the first n*4 bytes
    int local_or = 0;
    for (int i = t; i < n / 2; i += blockDim.x)
        local_or |= idx32[2 * i + 1];
    if (local_or) atomicOr(&odd_or, 1);
    __syncthreads();

    const int stride = (odd_or == 0) ? 2 : 1;   // 2 => int64 layout, 1 => int32

    for (int i = t; i < n; i += blockDim.x)
        atomicAdd(&cnt[idx32[i * stride] & (NEXP - 1)], 1);
    __syncthreads();

    if (t == 0) {
        int po = 0, tile = 0;
        for (int e = 0; e < NEXP; e++) {
            off[e] = po;
            cur[e] = 0;
            int ntl = (cnt[e] + BM - 1) / BM;
            for (int k = 0; k < ntl; k++) g_tile_expert[tile++] = e;
            po += ntl * BM;
        }
        for (; tile < MAX_TILES; tile++) g_tile_expert[tile] = -1;
    }
    __syncthreads();

    for (int i = t; i < PAD_TOK; i += blockDim.x) g_order[i] = -1;
    __syncthreads();

    for (int i = t; i < n; i += blockDim.x) {
        int e = idx32[i * stride] & (NEXP - 1);
        int p = off[e] + atomicAdd(&cur[e], 1);
        g_order[p] = i;
    }
}

// ---------------------------------------------------------------------------
// Pass 2: grouped GEMM. One block computes a BM x BN output tile for one
// expert. fp32 SIMT with smem tiling; 256 threads, 4x4 micro-tile each.
// ---------------------------------------------------------------------------
__global__ __launch_bounds__(256, 4)
void grouped_gemm_kernel(const float* __restrict__ X,   // (N_TOK, DIM)
                         const float* __restrict__ W,   // (NEXP, DIM, HOUT)
                         const float* __restrict__ Bv,  // (NEXP, HOUT)
                         float* __restrict__ Y)         // (N_TOK, HOUT)
{
    const int mt = blockIdx.x;
    const int nt = blockIdx.y;
    const int e  = g_tile_expert[mt];
    if (e < 0) return;

    __shared__ float As[BK][BM + 4];   // transposed: As[k][m]
    __shared__ float Bs[BK][BN];       // Bs[k][n]
    __shared__ int   toks[BM];

    const int tid = threadIdx.x;           // 0..255
    if (tid < BM) toks[tid] = g_order[mt * BM + tid];
    __syncthreads();

    const int ty = tid >> 4;               // 0..15 (m group)
    const int tx = tid & 15;               // 0..15 (n group)

    // A-load mapping: 4 threads per row, each loads a float4 of K
    const int am  = tid >> 2;              // row within tile 0..63
    const int ak  = (tid & 3) * 4;         // k offset 0,4,8,12
    const int a_tok = toks[am];
    const float* a_src = (a_tok >= 0) ? (X + (size_t)a_tok * DIM + ak) : nullptr;

    // B-load mapping: row = tid/16 (0..15), col = (tid%16)*4
    const int bk = tid >> 4;
    const int bn = (tid & 15) * 4;
    const float* Wb = W + (size_t)e * DIM * HOUT + (size_t)bk * HOUT + nt * BN + bn;

    float acc[4][4] = {};

    for (int k0 = 0; k0 < DIM; k0 += BK) {
        // load A tile (gathered rows), transposed into smem
        float4 av = make_float4(0.f, 0.f, 0.f, 0.f);
        if (a_src) av = *(const float4*)(a_src + k0);
        As[ak + 0][am] = av.x;
        As[ak + 1][am] = av.y;
        As[ak + 2][am] = av.z;
        As[ak + 3][am] = av.w;

        // load B tile (coalesced)
        float4 bv = *(const float4*)(Wb + (size_t)k0 * HOUT);
        *(float4*)&Bs[bk][bn] = bv;

        __syncthreads();

#pragma unroll
        for (int kk = 0; kk < BK; kk++) {
            const float a0 = As[kk][ty * 4 + 0];
            const float a1 = As[kk][ty * 4 + 1];
            const float a2 = As[kk][ty * 4 + 2];
            const float a3 = As[kk][ty * 4 + 3];
            const float4 b = *(const float4*)&Bs[kk][tx * 4];

            acc[0][0] += a0 * b.x; acc[0][1] += a0 * b.y; acc[0][2] += a0 * b.z; acc[0][3] += a0 * b.w;
            acc[1][0] += a1 * b.x; acc[1][1] += a1 * b.y; acc[1][2] += a1 * b.z; acc[1][3] += a1 * b.w;
            acc[2][0] += a2 * b.x; acc[2][1] += a2 * b.y; acc[2][2] += a2 * b.z; acc[2][3] += a2 * b.w;
            acc[3][0] += a3 * b.x; acc[3][1] += a3 * b.y; acc[3][2] += a3 * b.z; acc[3][3] += a3 * b.w;
        }
        __syncthreads();
    }

    // epilogue: bias + store (skip pad rows)
    const float4 bias = *(const float4*)(Bv + (size_t)e * HOUT + nt * BN + tx * 4);
#pragma unroll
    for (int i = 0; i < 4; i++) {
        const int tkn = toks[ty * 4 + i];
        if (tkn >= 0) {
            float4 o;
            o.x = acc[i][0] + bias.x;
            o.y = acc[i][1] + bias.y;
            o.z = acc[i][2] + bias.z;
            o.w = acc[i][3] + bias.w;
            *(float4*)(Y + (size_t)tkn * HOUT + nt * BN + tx * 4) = o;
        }
    }
}

extern "C" void kernel_launch(void* const* d_in, const int* in_sizes, int n_in,
                              void* d_out, int out_size)
{
    const float* X   = (const float*)d_in[0];   // inputs (2048, 512) f32
    const int*   idx = (const int*)d_in[1];     // idx (2048) i32 or i64 (autodetected)
    const float* W   = (const float*)d_in[2];   // weights (16, 512, 512) f32
    const float* Bv  = (const float*)d_in[3];   // biases (16, 512) f32
    float*       Y   = (float*)d_out;           // out (2048, 512) f32

    bucket_kernel<<<1, 256>>>(idx, N_TOK);

    dim3 grid(MAX_TILES, HOUT / BN);
    grouped_gemm_kernel<<<grid, 256>>>(X, W, Bv, Y);
}

// round 8
// speedup vs baseline: 1.4238x; 1.4238x over previous
#include <cuda_runtime.h>
#include <cuda_bf16.h>
#include <stdint.h>

// Problem constants
#define N_TOK   2048
#define DIM     512
#define HOUT    512
#define NEXP    16

// GEMM tiling
#define BM      128          // tokens per CTA tile
#define BN      64           // output cols per CTA tile
#define KC      64           // K chunk (bf16 elems) staged in smem
#define NCHUNK  (DIM / KC)   // 8
#define MAX_TILES 32         // ceil-sum over experts <= 2048/128 + 16
#define PAD_TOK (MAX_TILES * BM)

// smem tile layout (bf16 elements), padded stride 72 (=144B, conflict-free ldmatrix)
#define LDS     72
#define A_HI_E  0
#define A_LO_E  (BM * LDS)               //  9216
#define B_HI_E  (2 * BM * LDS)           // 18432
#define B_LO_E  (B_HI_E + KC * LDS)      // 23040
#define SMEM_ELE (B_LO_E + KC * LDS)     // 27648 bf16
#define SMEM_BYTES (SMEM_ELE * 2)        // 55296

// Split-bf16 scratch (device globals; uint4 for 16B alignment)
#define WELEMS (NEXP * DIM * HOUT)       // 4194304
#define XELEMS (N_TOK * DIM)             // 1048576
__device__ uint4 g_Whi4[WELEMS / 8];
__device__ uint4 g_Wlo4[WELEMS / 8];
__device__ uint4 g_Xhi4[XELEMS / 8];
__device__ uint4 g_Xlo4[XELEMS / 8];

__device__ int g_order[PAD_TOK];
__device__ int g_tile_expert[MAX_TILES];

// ---------------------------------------------------------------------------
// PTX helpers (sm_80-era instructions only; no sm_103a-gated features)
// ---------------------------------------------------------------------------
__device__ __forceinline__ uint32_t smem_u32(const void* p) {
    uint32_t a;
    asm("{ .reg .u64 t; cvta.to.shared.u64 t, %1; cvt.u32.u64 %0, t; }"
        : "=r"(a) : "l"(p));
    return a;
}
__device__ __forceinline__ void ldsm_x4(uint32_t* r, uint32_t addr) {
    asm volatile("ldmatrix.sync.aligned.m8n8.x4.shared.b16 {%0,%1,%2,%3}, [%4];"
                 : "=r"(r[0]), "=r"(r[1]), "=r"(r[2]), "=r"(r[3]) : "r"(addr));
}
__device__ __forceinline__ void ldsm_x4_t(uint32_t* r, uint32_t addr) {
    asm volatile("ldmatrix.sync.aligned.m8n8.x4.trans.shared.b16 {%0,%1,%2,%3}, [%4];"
                 : "=r"(r[0]), "=r"(r[1]), "=r"(r[2]), "=r"(r[3]) : "r"(addr));
}
__device__ __forceinline__ void mma_bf16(float* c, const uint32_t* a,
                                         uint32_t b0, uint32_t b1) {
    asm volatile(
        "mma.sync.aligned.m16n8k16.row.col.f32.bf16.bf16.f32 "
        "{%0,%1,%2,%3}, {%4,%5,%6,%7}, {%8,%9}, {%0,%1,%2,%3};"
        : "+f"(c[0]), "+f"(c[1]), "+f"(c[2]), "+f"(c[3])
        : "r"(a[0]), "r"(a[1]), "r"(a[2]), "r"(a[3]), "r"(b0), "r"(b1));
}

// ---------------------------------------------------------------------------
// Pass 1: bucket tokens by expert (int64-vs-int32 idx autodetect; proven).
// ---------------------------------------------------------------------------
__global__ void bucket_kernel(const int* __restrict__ idx32, int n)
{
    __shared__ int cnt[NEXP];
    __shared__ int off[NEXP];
    __shared__ int cur[NEXP];
    __shared__ int odd_or;
    const int t = threadIdx.x;

    if (t == 0) odd_or = 0;
    if (t < NEXP) cnt[t] = 0;
    __syncthreads();

    int local_or = 0;
    for (int i = t; i < n / 2; i += blockDim.x)
        local_or |= idx32[2 * i + 1];
    if (local_or) atomicOr(&odd_or, 1);
    __syncthreads();

    const int stride = (odd_or == 0) ? 2 : 1;

    for (int i = t; i < n; i += blockDim.x)
        atomicAdd(&cnt[idx32[i * stride] & (NEXP - 1)], 1);
    __syncthreads();

    if (t == 0) {
        int po = 0, tile = 0;
        for (int e = 0; e < NEXP; e++) {
            off[e] = po;
            cur[e] = 0;
            int ntl = (cnt[e] + BM - 1) / BM;
            for (int k = 0; k < ntl; k++) g_tile_expert[tile++] = e;
            po += ntl * BM;
        }
        for (; tile < MAX_TILES; tile++) g_tile_expert[tile] = -1;
    }
    __syncthreads();

    for (int i = t; i < PAD_TOK; i += blockDim.x) g_order[i] = -1;
    __syncthreads();

    for (int i = t; i < n; i += blockDim.x) {
        int e = idx32[i * stride] & (NEXP - 1);
        int p = off[e] + atomicAdd(&cur[e], 1);
        g_order[p] = i;
    }
}

// ---------------------------------------------------------------------------
// Pass 2: fp32 -> bf16 hi/lo split of W and X (pure streaming).
// Each thread handles 8 floats -> one uint4 of hi + one uint4 of lo.
// ---------------------------------------------------------------------------
__global__ void convert_kernel(const float4* __restrict__ W,
                               const float4* __restrict__ X)
{
    const int i = blockIdx.x * blockDim.x + threadIdx.x;
    const int W8 = WELEMS / 8;
    const int X8 = XELEMS / 8;
    if (i >= W8 + X8) return;

    const float4* src;
    uint4 *dh, *dl;
    int j;
    if (i < W8) { j = i;      src = W; dh = g_Whi4 + j; dl = g_Wlo4 + j; }
    else        { j = i - W8; src = X; dh = g_Xhi4 + j; dl = g_Xlo4 + j; }

    float4 v0 = src[2 * j];
    float4 v1 = src[2 * j + 1];
    float f[8] = {v0.x, v0.y, v0.z, v0.w, v1.x, v1.y, v1.z, v1.w};

    __nv_bfloat16 h[8], l[8];
#pragma unroll
    for (int q = 0; q < 8; q++) {
        h[q] = __float2bfloat16(f[q]);
        l[q] = __float2bfloat16(f[q] - __bfloat162float(h[q]));
    }
    uint4 uh, ul;
    uh.x = ((uint32_t)*(uint16_t*)&h[1] << 16) | *(uint16_t*)&h[0];
    uh.y = ((uint32_t)*(uint16_t*)&h[3] << 16) | *(uint16_t*)&h[2];
    uh.z = ((uint32_t)*(uint16_t*)&h[5] << 16) | *(uint16_t*)&h[4];
    uh.w = ((uint32_t)*(uint16_t*)&h[7] << 16) | *(uint16_t*)&h[6];
    ul.x = ((uint32_t)*(uint16_t*)&l[1] << 16) | *(uint16_t*)&l[0];
    ul.y = ((uint32_t)*(uint16_t*)&l[3] << 16) | *(uint16_t*)&l[2];
    ul.z = ((uint32_t)*(uint16_t*)&l[5] << 16) | *(uint16_t*)&l[4];
    ul.w = ((uint32_t)*(uint16_t*)&l[7] << 16) | *(uint16_t*)&l[6];
    *dh = uh;
    *dl = ul;
}

// ---------------------------------------------------------------------------
// Pass 3: HMMA grouped GEMM, split-bf16 (hi*hi + hi*lo + lo*hi).
// CTA = 128 tokens x 64 cols; 8 warps of 32x32; K chunked by 64 via smem.
// ---------------------------------------------------------------------------
__global__ __launch_bounds__(256, 2)
void gemm_hmma_kernel(const float* __restrict__ Bv, float* __restrict__ Y)
{
    extern __shared__ __nv_bfloat16 sm[];
    __shared__ int toks[BM];

    const int mt = blockIdx.x;
    const int nt = blockIdx.y;
    const int e  = g_tile_expert[mt];
    if (e < 0) return;

    const int tid = threadIdx.x;
    const int wid = tid >> 5;
    const int lid = tid & 31;
    const int ntb = nt * BN;

    if (tid < BM) toks[tid] = g_order[mt * BM + tid];
    __syncthreads();

    const __nv_bfloat16* Xhi = (const __nv_bfloat16*)g_Xhi4;
    const __nv_bfloat16* Xlo = (const __nv_bfloat16*)g_Xlo4;
    const __nv_bfloat16* Whi = (const __nv_bfloat16*)g_Whi4 + (size_t)e * DIM * HOUT + ntb;
    const __nv_bfloat16* Wlo = (const __nv_bfloat16*)g_Wlo4 + (size_t)e * DIM * HOUT + ntb;

    // per-warp tile: warp_m in 0..3 (32 rows), warp_n in 0..1 (32 cols)
    const int m_base = (wid >> 1) * 32;
    const int n_base = (wid & 1) * 32;

    const uint32_t sbase = smem_u32(sm);
    // ldmatrix lane addressing (standard sm80 pattern)
    const uint32_t a_row  = m_base + (lid & 15);
    const uint32_t a_coff = (lid >> 4) << 3;
    const uint32_t aAddr  = sbase + (uint32_t)(a_row * LDS + a_coff) * 2;
    const uint32_t b_krow = (lid & 15);
    const uint32_t b_coff = n_base + ((lid >> 4) << 3);
    const uint32_t bAddr  = sbase + (uint32_t)(B_HI_E + b_krow * LDS + b_coff) * 2;

    float acc[2][4][4] = {};

    for (int c = 0; c < NCHUNK; c++) {
        const int k0 = c * KC;

        // ---- load chunk into smem (hi & lo) ----
        // A: 128 rows x 64 bf16 = 1024 x 16B vectors; 4 per thread
#pragma unroll
        for (int t = 0; t < 4; t++) {
            int i = tid + t * 256;
            int row = i >> 3;
            int c8 = (i & 7) * 8;
            int tok = toks[row];
            uint4 vh = make_uint4(0, 0, 0, 0), vl = vh;
            if (tok >= 0) {
                size_t src = (size_t)tok * DIM + k0 + c8;
                vh = *(const uint4*)(Xhi + src);
                vl = *(const uint4*)(Xlo + src);
            }
            *(uint4*)(sm + A_HI_E + row * LDS + c8) = vh;
            *(uint4*)(sm + A_LO_E + row * LDS + c8) = vl;
        }
        // B: 64 k-rows x 64 bf16 = 512 x 16B vectors; 2 per thread
#pragma unroll
        for (int t = 0; t < 2; t++) {
            int i = tid + t * 256;
            int row = i >> 3;
            int c8 = (i & 7) * 8;
            size_t src = (size_t)(k0 + row) * HOUT + c8;
            *(uint4*)(sm + B_HI_E + row * LDS + c8) = *(const uint4*)(Whi + src);
            *(uint4*)(sm + B_LO_E + row * LDS + c8) = *(const uint4*)(Wlo + src);
        }
        __syncthreads();

        // ---- compute: 4 k-steps of 16 ----
#pragma unroll
        for (int ks = 0; ks < 4; ks++) {
            uint32_t ah[2][4], al[2][4], bh[2][4], bl[2][4];
#pragma unroll
            for (int mi = 0; mi < 2; mi++) {
                uint32_t ad = aAddr + (uint32_t)(mi * 16 * LDS + ks * 16) * 2;
                ldsm_x4(ah[mi], ad);
                ldsm_x4(al[mi], ad + A_LO_E * 2);
            }
#pragma unroll
            for (int np = 0; np < 2; np++) {
                uint32_t bd = bAddr + (uint32_t)(ks * 16 * LDS + np * 16) * 2;
                ldsm_x4_t(bh[np], bd);
                ldsm_x4_t(bl[np], bd + (B_LO_E - B_HI_E) * 2);
            }
#pragma unroll
            for (int mi = 0; mi < 2; mi++)
#pragma unroll
                for (int ni = 0; ni < 4; ni++) {
                    const int np = ni >> 1, hf = (ni & 1) * 2;
                    mma_bf16(acc[mi][ni], ah[mi], bh[np][hf], bh[np][hf + 1]);
                    mma_bf16(acc[mi][ni], ah[mi], bl[np][hf], bl[np][hf + 1]);
                    mma_bf16(acc[mi][ni], al[mi], bh[np][hf], bh[np][hf + 1]);
                }
        }
        __syncthreads();
    }

    // ---- epilogue: bias + gathered store ----
#pragma unroll
    for (int mi = 0; mi < 2; mi++) {
        const int r0 = m_base + mi * 16 + (lid >> 2);
        const int tok0 = toks[r0];
        const int tok1 = toks[r0 + 8];
#pragma unroll
        for (int ni = 0; ni < 4; ni++) {
            const int col = ntb + n_base + ni * 8 + (lid & 3) * 2;
            const float2 b2 = *(const float2*)(Bv + (size_t)e * HOUT + col);
            if (tok0 >= 0) {
                float2 o = {acc[mi][ni][0] + b2.x, acc[mi][ni][1] + b2.y};
                *(float2*)(Y + (size_t)tok0 * HOUT + col) = o;
            }
            if (tok1 >= 0) {
                float2 o = {acc[mi][ni][2] + b2.x, acc[mi][ni][3] + b2.y};
                *(float2*)(Y + (size_t)tok1 * HOUT + col) = o;
            }
        }
    }
}

extern "C" void kernel_launch(void* const* d_in, const int* in_sizes, int n_in,
                              void* d_out, int out_size)
{
    const float* X   = (const float*)d_in[0];   // inputs (2048, 512) f32
    const int*   idx = (const int*)d_in[1];     // idx (2048) i32/i64 autodetect
    const float* W   = (const float*)d_in[2];   // weights (16, 512, 512) f32
    const float* Bv  = (const float*)d_in[3];   // biases (16, 512) f32
    float*       Y   = (float*)d_out;           // out (2048, 512) f32

    static bool attr_done = false;
    cudaFuncSetAttribute(gemm_hmma_kernel,
                         cudaFuncAttributeMaxDynamicSharedMemorySize, SMEM_BYTES);
    (void)attr_done;

    bucket_kernel<<<1, 256>>>(idx, N_TOK);

    const int conv_threads = (WELEMS + XELEMS) / 8;
    convert_kernel<<<(conv_threads + 255) / 256, 256>>>((const float4*)W,
                                                        (const float4*)X);

    dim3 grid(MAX_TILES, HOUT / BN);
    gemm_hmma_kernel<<<grid, 256, SMEM_BYTES>>>(Bv, Y);
}

// round 9
// speedup vs baseline: 1.6595x; 1.1655x over previous
#include <cuda_runtime.h>
#include <cuda_bf16.h>
#include <stdint.h>

// Problem constants
#define N_TOK   2048
#define DIM     512
#define HOUT    512
#define NEXP    16

// GEMM tiling
#define BM      128          // tokens per CTA tile
#define BN      64           // output cols per CTA tile
#define KC      64           // K chunk (bf16 elems) staged in smem
#define NCHUNK  (DIM / KC)   // 8
#define MAX_TILES 32
#define PAD_TOK (MAX_TILES * BM)

// smem tile layout per stage (bf16 elems), stride 72 (144B: conflict-free ldmatrix)
#define LDS     72
#define A_HI_E  0
#define A_LO_E  (BM * LDS)               //  9216
#define B_HI_E  (2 * BM * LDS)           // 18432
#define B_LO_E  (B_HI_E + KC * LDS)      // 23040
#define STG_E   (B_LO_E + KC * LDS)      // 27648 bf16 per stage
#define SMEM_BYTES (2 * STG_E * 2)       // 110592 (double buffered)

// Split-bf16 scratch
#define WELEMS (NEXP * DIM * HOUT)       // 4194304
#define XELEMS (N_TOK * DIM)             // 1048576
__device__ uint4 g_Whi4[WELEMS / 8];
__device__ uint4 g_Wlo4[WELEMS / 8];
__device__ uint4 g_Xhi4[XELEMS / 8];
__device__ uint4 g_Xlo4[XELEMS / 8];

__device__ int g_order[PAD_TOK];
__device__ int g_tile_expert[MAX_TILES];

// ---------------------------------------------------------------------------
// PTX helpers (sm_80-era only; tcgen05 is gated off by the harness's sm_103
// ptxas target)
// ---------------------------------------------------------------------------
__device__ __forceinline__ uint32_t smem_u32(const void* p) {
    uint32_t a;
    asm("{ .reg .u64 t; cvta.to.shared.u64 t, %1; cvt.u32.u64 %0, t; }"
        : "=r"(a) : "l"(p));
    return a;
}
__device__ __forceinline__ void ldsm_x4(uint32_t* r, uint32_t addr) {
    asm volatile("ldmatrix.sync.aligned.m8n8.x4.shared.b16 {%0,%1,%2,%3}, [%4];"
                 : "=r"(r[0]), "=r"(r[1]), "=r"(r[2]), "=r"(r[3]) : "r"(addr));
}
__device__ __forceinline__ void ldsm_x4_t(uint32_t* r, uint32_t addr) {
    asm volatile("ldmatrix.sync.aligned.m8n8.x4.trans.shared.b16 {%0,%1,%2,%3}, [%4];"
                 : "=r"(r[0]), "=r"(r[1]), "=r"(r[2]), "=r"(r[3]) : "r"(addr));
}
__device__ __forceinline__ void mma_bf16(float* c, const uint32_t* a,
                                         uint32_t b0, uint32_t b1) {
    asm volatile(
        "mma.sync.aligned.m16n8k16.row.col.f32.bf16.bf16.f32 "
        "{%0,%1,%2,%3}, {%4,%5,%6,%7}, {%8,%9}, {%0,%1,%2,%3};"
        : "+f"(c[0]), "+f"(c[1]), "+f"(c[2]), "+f"(c[3])
        : "r"(a[0]), "r"(a[1]), "r"(a[2]), "r"(a[3]), "r"(b0), "r"(b1));
}
__device__ __forceinline__ void cp16(uint32_t dst, const void* src,
                                     uint32_t src_bytes) {
    asm volatile("cp.async.cg.shared.global [%0], [%1], 16, %2;"
                 :: "r"(dst), "l"(src), "r"(src_bytes) : "memory");
}
__device__ __forceinline__ void cp_commit() {
    asm volatile("cp.async.commit_group;" ::: "memory");
}
template <int N>
__device__ __forceinline__ void cp_wait() {
    asm volatile("cp.async.wait_group %0;" :: "n"(N) : "memory");
}

// ---------------------------------------------------------------------------
// Bucket logic (proven): runs inside one 256-thread block.
// ---------------------------------------------------------------------------
__device__ void bucket_block(const int* __restrict__ idx32, int n)
{
    __shared__ int cnt[NEXP];
    __shared__ int off[NEXP];
    __shared__ int cur[NEXP];
    __shared__ int odd_or;
    const int t = threadIdx.x;

    if (t == 0) odd_or = 0;
    if (t < NEXP) cnt[t] = 0;
    __syncthreads();

    int local_or = 0;
    for (int i = t; i < n / 2; i += 256)
        local_or |= idx32[2 * i + 1];
    if (local_or) atomicOr(&odd_or, 1);
    __syncthreads();

    const int stride = (odd_or == 0) ? 2 : 1;

    for (int i = t; i < n; i += 256)
        atomicAdd(&cnt[idx32[i * stride] & (NEXP - 1)], 1);
    __syncthreads();

    if (t == 0) {
        int po = 0, tile = 0;
        for (int e = 0; e < NEXP; e++) {
            off[e] = po;
            cur[e] = 0;
            int ntl = (cnt[e] + BM - 1) / BM;
            for (int k = 0; k < ntl; k++) g_tile_expert[tile++] = e;
            po += ntl * BM;
        }
        for (; tile < MAX_TILES; tile++) g_tile_expert[tile] = -1;
    }
    __syncthreads();

    for (int i = t; i < PAD_TOK; i += 256) g_order[i] = -1;
    __syncthreads();

    for (int i = t; i < n; i += 256) {
        int e = idx32[i * stride] & (NEXP - 1);
        int p = off[e] + atomicAdd(&cur[e], 1);
        g_order[p] = i;
    }
}

// ---------------------------------------------------------------------------
// Pass 1 (fused): blocks [0, 2560) convert W & X to bf16 hi/lo; the last
// block does the (independent) bucketing. Bucket latency hides under the
// DRAM-bound convert.
// ---------------------------------------------------------------------------
#define CONV_BLOCKS ((WELEMS + XELEMS) / 8 / 256)   // 2560

__global__ void prep_kernel(const float4* __restrict__ W,
                            const float4* __restrict__ X,
                            const int* __restrict__ idx32)
{
    if (blockIdx.x == CONV_BLOCKS) {
        bucket_block(idx32, N_TOK);
        return;
    }

    const int i = blockIdx.x * 256 + threadIdx.x;
    const int W8 = WELEMS / 8;

    const float4* src;
    uint4 *dh, *dl;
    int j;
    if (i < W8) { j = i;      src = W; dh = g_Whi4 + j; dl = g_Wlo4 + j; }
    else        { j = i - W8; src = X; dh = g_Xhi4 + j; dl = g_Xlo4 + j; }

    float4 v0 = src[2 * j];
    float4 v1 = src[2 * j + 1];
    float f[8] = {v0.x, v0.y, v0.z, v0.w, v1.x, v1.y, v1.z, v1.w};

    __nv_bfloat16 h[8], l[8];
#pragma unroll
    for (int q = 0; q < 8; q++) {
        h[q] = __float2bfloat16(f[q]);
        l[q] = __float2bfloat16(f[q] - __bfloat162float(h[q]));
    }
    uint4 uh, ul;
    uh.x = ((uint32_t)*(uint16_t*)&h[1] << 16) | *(uint16_t*)&h[0];
    uh.y = ((uint32_t)*(uint16_t*)&h[3] << 16) | *(uint16_t*)&h[2];
    uh.z = ((uint32_t)*(uint16_t*)&h[5] << 16) | *(uint16_t*)&h[4];
    uh.w = ((uint32_t)*(uint16_t*)&h[7] << 16) | *(uint16_t*)&h[6];
    ul.x = ((uint32_t)*(uint16_t*)&l[1] << 16) | *(uint16_t*)&l[0];
    ul.y = ((uint32_t)*(uint16_t*)&l[3] << 16) | *(uint16_t*)&l[2];
    ul.z = ((uint32_t)*(uint16_t*)&l[5] << 16) | *(uint16_t*)&l[4];
    ul.w = ((uint32_t)*(uint16_t*)&l[7] << 16) | *(uint16_t*)&l[6];
    *dh = uh;
    *dl = ul;
}

// ---------------------------------------------------------------------------
// Pass 2: HMMA grouped GEMM, split-bf16, cp.async double-buffered mainloop.
// ---------------------------------------------------------------------------
__device__ __forceinline__ void stage_chunk(uint32_t sdst,   // smem stage base
                                            int c,
                                            const __nv_bfloat16* Xhi,
                                            const __nv_bfloat16* Xlo,
                                            const __nv_bfloat16* Whi,
                                            const __nv_bfloat16* Wlo,
                                            const int* toks, int tid)
{
    const int k0 = c * KC;
    // A: 128 rows x 64 bf16 -> 1024 16B vectors; 4 per thread (hi+lo)
#pragma unroll
    for (int t = 0; t < 4; t++) {
        int i = tid + t * 256;
        int row = i >> 3;
        int c8 = (i & 7) * 8;
        int tok = toks[row];
        uint32_t nb = (tok >= 0) ? 16u : 0u;   // zero-fill pad rows
        size_t src = (size_t)(tok >= 0 ? tok : 0) * DIM + k0 + c8;
        uint32_t d = sdst + (uint32_t)(A_HI_E + row * LDS + c8) * 2;
        cp16(d, Xhi + src, nb);
        cp16(d + (uint32_t)(A_LO_E - A_HI_E) * 2, Xlo + src, nb);
    }
    // B: 64 k-rows x 64 bf16 -> 512 16B vectors; 2 per thread (hi+lo)
#pragma unroll
    for (int t = 0; t < 2; t++) {
        int i = tid + t * 256;
        int row = i >> 3;
        int c8 = (i & 7) * 8;
        size_t src = (size_t)(k0 + row) * HOUT + c8;
        uint32_t d = sdst + (uint32_t)(B_HI_E + row * LDS + c8) * 2;
        cp16(d, Whi + src, 16u);
        cp16(d + (uint32_t)(B_LO_E - B_HI_E) * 2, Wlo + src, 16u);
    }
    cp_commit();
}

__global__ __launch_bounds__(256, 2)
void gemm_hmma_kernel(const float* __restrict__ Bv, float* __restrict__ Y)
{
    extern __shared__ __nv_bfloat16 sm[];
    __shared__ int toks[BM];

    const int mt = blockIdx.x;
    const int nt = blockIdx.y;
    const int e  = g_tile_expert[mt];
    if (e < 0) return;

    const int tid = threadIdx.x;
    const int wid = tid >> 5;
    const int lid = tid & 31;
    const int ntb = nt * BN;

    if (tid < BM) toks[tid] = g_order[mt * BM + tid];
    __syncthreads();

    const __nv_bfloat16* Xhi = (const __nv_bfloat16*)g_Xhi4;
    const __nv_bfloat16* Xlo = (const __nv_bfloat16*)g_Xlo4;
    const __nv_bfloat16* Whi = (const __nv_bfloat16*)g_Whi4 + (size_t)e * DIM * HOUT + ntb;
    const __nv_bfloat16* Wlo = (const __nv_bfloat16*)g_Wlo4 + (size_t)e * DIM * HOUT + ntb;

    const int m_base = (wid >> 1) * 32;
    const int n_base = (wid & 1) * 32;

    const uint32_t sbase = smem_u32(sm);
    const uint32_t a_row  = m_base + (lid & 15);
    const uint32_t a_coff = (lid >> 4) << 3;
    const uint32_t aAddr  = sbase + (uint32_t)(a_row * LDS + a_coff) * 2;
    const uint32_t b_krow = (lid & 15);
    const uint32_t b_coff = n_base + ((lid >> 4) << 3);
    const uint32_t bAddr  = sbase + (uint32_t)(B_HI_E + b_krow * LDS + b_coff) * 2;

    float acc[2][4][4] = {};

    // prologue: stage chunk 0
    stage_chunk(sbase, 0, Xhi, Xlo, Whi, Wlo, toks, tid);

    for (int c = 0; c < NCHUNK; c++) {
        const uint32_t soff = (uint32_t)((c & 1) * STG_E) * 2;

        if (c + 1 < NCHUNK)
            stage_chunk(sbase + (uint32_t)(((c + 1) & 1) * STG_E) * 2,
                        c + 1, Xhi, Xlo, Whi, Wlo, toks, tid);

        if (c + 1 < NCHUNK) cp_wait<1>(); else cp_wait<0>();
        __syncthreads();

#pragma unroll
        for (int ks = 0; ks < 4; ks++) {
            uint32_t ah[2][4], al[2][4], bh[2][4], bl[2][4];
#pragma unroll
            for (int mi = 0; mi < 2; mi++) {
                uint32_t ad = aAddr + soff + (uint32_t)(mi * 16 * LDS + ks * 16) * 2;
                ldsm_x4(ah[mi], ad);
                ldsm_x4(al[mi], ad + A_LO_E * 2);
            }
#pragma unroll
            for (int np = 0; np < 2; np++) {
                uint32_t bd = bAddr + soff + (uint32_t)(ks * 16 * LDS + np * 16) * 2;
                ldsm_x4_t(bh[np], bd);
                ldsm_x4_t(bl[np], bd + (B_LO_E - B_HI_E) * 2);
            }
#pragma unroll
            for (int mi = 0; mi < 2; mi++)
#pragma unroll
                for (int ni = 0; ni < 4; ni++) {
                    const int np = ni >> 1, hf = (ni & 1) * 2;
                    mma_bf16(acc[mi][ni], ah[mi], bh[np][hf], bh[np][hf + 1]);
                    mma_bf16(acc[mi][ni], ah[mi], bl[np][hf], bl[np][hf + 1]);
                    mma_bf16(acc[mi][ni], al[mi], bh[np][hf], bh[np][hf + 1]);
                }
        }
        __syncthreads();
    }

    // epilogue: bias + gathered store
#pragma unroll
    for (int mi = 0; mi < 2; mi++) {
        const int r0 = m_base + mi * 16 + (lid >> 2);
        const int tok0 = toks[r0];
        const int tok1 = toks[r0 + 8];
#pragma unroll
        for (int ni = 0; ni < 4; ni++) {
            const int col = ntb + n_base + ni * 8 + (lid & 3) * 2;
            const float2 b2 = *(const float2*)(Bv + (size_t)e * HOUT + col);
            if (tok0 >= 0) {
                float2 o = {acc[mi][ni][0] + b2.x, acc[mi][ni][1] + b2.y};
                *(float2*)(Y + (size_t)tok0 * HOUT + col) = o;
            }
            if (tok1 >= 0) {
                float2 o = {acc[mi][ni][2] + b2.x, acc[mi][ni][3] + b2.y};
                *(float2*)(Y + (size_t)tok1 * HOUT + col) = o;
            }
        }
    }
}

extern "C" void kernel_launch(void* const* d_in, const int* in_sizes, int n_in,
                              void* d_out, int out_size)
{
    const float* X   = (const float*)d_in[0];   // inputs (2048, 512) f32
    const int*   idx = (const int*)d_in[1];     // idx (2048) i32/i64 autodetect
    const float* W   = (const float*)d_in[2];   // weights (16, 512, 512) f32
    const float* Bv  = (const float*)d_in[3];   // biases (16, 512) f32
    float*       Y   = (float*)d_out;           // out (2048, 512) f32

    cudaFuncSetAttribute(gemm_hmma_kernel,
                         cudaFuncAttributeMaxDynamicSharedMemorySize, SMEM_BYTES);

    prep_kernel<<<CONV_BLOCKS + 1, 256>>>((const float4*)W, (const float4*)X, idx);

    dim3 grid(MAX_TILES, HOUT / BN);
    gemm_hmma_kernel<<<grid, 256, SMEM_BYTES>>>(Bv, Y);
}

// round 10
// speedup vs baseline: 1.7752x; 1.0697x over previous
#include <cuda_runtime.h>
#include <cuda_bf16.h>
#include <stdint.h>

// Problem constants
#define N_TOK   2048
#define DIM     512
#define HOUT    512
#define NEXP    16

// GEMM tiling
#define BM      128          // tokens per CTA tile
#define BN      64           // output cols per CTA tile
#define KC      32           // K chunk (bf16 elems) staged in smem
#define NCHUNK  (DIM / KC)   // 16
#define NSTAGE  3
#define MAX_TILES 32
#define PAD_TOK (MAX_TILES * BM)

// smem per-stage layout (bf16 elems)
#define LDSA    40           // KC + 8 pad (80B rows: conflict-free ldmatrix)
#define LDSB    72           // BN + 8 pad (144B rows: proven conflict-free)
#define A_HI_E  0
#define A_LO_E  (BM * LDSA)              //  5120
#define B_HI_E  (2 * BM * LDSA)          // 10240
#define B_LO_E  (B_HI_E + KC * LDSB)     // 12544
#define STG_E   (B_LO_E + KC * LDSB)     // 14848 bf16 = 29696 B
#define SMEM_BYTES (NSTAGE * STG_E * 2)  // 89088

// Split-bf16 scratch
#define WELEMS (NEXP * DIM * HOUT)       // 4194304
#define XELEMS (N_TOK * DIM)             // 1048576
__device__ uint4 g_Whi4[WELEMS / 8];
__device__ uint4 g_Wlo4[WELEMS / 8];
__device__ uint4 g_Xhi4[XELEMS / 8];
__device__ uint4 g_Xlo4[XELEMS / 8];

__device__ int g_order[PAD_TOK];
__device__ int g_tile_expert[MAX_TILES];

// ---------------------------------------------------------------------------
// PTX helpers (sm_80-era only; tcgen05 is gated off by the sm_103 ptxas target)
// ---------------------------------------------------------------------------
__device__ __forceinline__ uint32_t smem_u32(const void* p) {
    uint32_t a;
    asm("{ .reg .u64 t; cvta.to.shared.u64 t, %1; cvt.u32.u64 %0, t; }"
        : "=r"(a) : "l"(p));
    return a;
}
__device__ __forceinline__ void ldsm_x4(uint32_t* r, uint32_t addr) {
    asm volatile("ldmatrix.sync.aligned.m8n8.x4.shared.b16 {%0,%1,%2,%3}, [%4];"
                 : "=r"(r[0]), "=r"(r[1]), "=r"(r[2]), "=r"(r[3]) : "r"(addr));
}
__device__ __forceinline__ void ldsm_x4_t(uint32_t* r, uint32_t addr) {
    asm volatile("ldmatrix.sync.aligned.m8n8.x4.trans.shared.b16 {%0,%1,%2,%3}, [%4];"
                 : "=r"(r[0]), "=r"(r[1]), "=r"(r[2]), "=r"(r[3]) : "r"(addr));
}
__device__ __forceinline__ void mma_bf16(float* c, const uint32_t* a,
                                         uint32_t b0, uint32_t b1) {
    asm volatile(
        "mma.sync.aligned.m16n8k16.row.col.f32.bf16.bf16.f32 "
        "{%0,%1,%2,%3}, {%4,%5,%6,%7}, {%8,%9}, {%0,%1,%2,%3};"
        : "+f"(c[0]), "+f"(c[1]), "+f"(c[2]), "+f"(c[3])
        : "r"(a[0]), "r"(a[1]), "r"(a[2]), "r"(a[3]), "r"(b0), "r"(b1));
}
__device__ __forceinline__ void cp16(uint32_t dst, const void* src,
                                     uint32_t src_bytes) {
    asm volatile("cp.async.cg.shared.global [%0], [%1], 16, %2;"
                 :: "r"(dst), "l"(src), "r"(src_bytes) : "memory");
}
__device__ __forceinline__ void cp_commit() {
    asm volatile("cp.async.commit_group;" ::: "memory");
}
template <int N>
__device__ __forceinline__ void cp_wait() {
    asm volatile("cp.async.wait_group %0;" :: "n"(N) : "memory");
}

// ---------------------------------------------------------------------------
// Fast bucketing: everything in smem, one block. Global traffic ~32KB.
// Handles int64-vs-int32 idx via odd-word detection (two-phase load: never
// reads beyond 2048 words unless the int64 pattern is confirmed).
// ---------------------------------------------------------------------------
__device__ void bucket_block_fast(const int* __restrict__ idx32)
{
    __shared__ int w[2 * N_TOK];       // raw words (16KB)
    __shared__ int ord[PAD_TOK];       // staged order (16KB)
    __shared__ int cnt[NEXP], off[NEXP], cur[NEXP];
    __shared__ int odd_or;
    const int t = threadIdx.x;

    if (t == 0) odd_or = 0;
    if (t < NEXP) { cnt[t] = 0; cur[t] = 0; }

    // phase 1: first 2048 words (always safe: idx is >= 2048 ints)
    for (int i = t; i < N_TOK; i += 256) w[i] = idx32[i];
    __syncthreads();

    int lor = 0;
    for (int i = t; i < N_TOK / 2; i += 256) lor |= w[2 * i + 1];
    if (lor) atomicOr(&odd_or, 1);
    __syncthreads();

    const int stride = (odd_or == 0) ? 2 : 1;
    if (stride == 2) {   // int64: load the remaining 2048 words
        for (int i = t; i < N_TOK; i += 256) w[N_TOK + i] = idx32[N_TOK + i];
        __syncthreads();
    }

    // counts (smem atomics)
    for (int i = t; i < N_TOK; i += 256)
        atomicAdd(&cnt[w[i * stride] & (NEXP - 1)], 1);
    for (int i = t; i < PAD_TOK; i += 256) ord[i] = -1;
    __syncthreads();

    // prefix + tile map (serial over 16; trivial)
    if (t == 0) {
        int po = 0, tile = 0;
        for (int e = 0; e < NEXP; e++) {
            off[e] = po;
            int ntl = (cnt[e] + BM - 1) / BM;
            for (int k = 0; k < ntl; k++) g_tile_expert[tile++] = e;
            po += ntl * BM;
        }
        for (; tile < MAX_TILES; tile++) g_tile_expert[tile] = -1;
    }
    __syncthreads();

    // scatter into smem order
    for (int i = t; i < N_TOK; i += 256) {
        int e = w[i * stride] & (NEXP - 1);
        ord[off[e] + atomicAdd(&cur[e], 1)] = i;
    }
    __syncthreads();

    // coalesced writeback
    for (int i = t; i < PAD_TOK; i += 256) g_order[i] = ord[i];
}

// ---------------------------------------------------------------------------
// Pass 1 (fused): block 0 buckets; blocks [1, CONV_BLOCKS] convert W & X
// to bf16 hi/lo.
// ---------------------------------------------------------------------------
#define CONV_BLOCKS ((WELEMS + XELEMS) / 8 / 256)   // 2560

__global__ void prep_kernel(const float4* __restrict__ W,
                            const float4* __restrict__ X,
                            const int* __restrict__ idx32)
{
    if (blockIdx.x == 0) {
        bucket_block_fast(idx32);
        return;
    }

    const int i = (blockIdx.x - 1) * 256 + threadIdx.x;
    const int W8 = WELEMS / 8;

    const float4* src;
    uint4 *dh, *dl;
    int j;
    if (i < W8) { j = i;      src = W; dh = g_Whi4 + j; dl = g_Wlo4 + j; }
    else        { j = i - W8; src = X; dh = g_Xhi4 + j; dl = g_Xlo4 + j; }

    float4 v0 = src[2 * j];
    float4 v1 = src[2 * j + 1];
    float f[8] = {v0.x, v0.y, v0.z, v0.w, v1.x, v1.y, v1.z, v1.w};

    __nv_bfloat16 h[8], l[8];
#pragma unroll
    for (int q = 0; q < 8; q++) {
        h[q] = __float2bfloat16(f[q]);
        l[q] = __float2bfloat16(f[q] - __bfloat162float(h[q]));
    }
    uint4 uh, ul;
    uh.x = ((uint32_t)*(uint16_t*)&h[1] << 16) | *(uint16_t*)&h[0];
    uh.y = ((uint32_t)*(uint16_t*)&h[3] << 16) | *(uint16_t*)&h[2];
    uh.z = ((uint32_t)*(uint16_t*)&h[5] << 16) | *(uint16_t*)&h[4];
    uh.w = ((uint32_t)*(uint16_t*)&h[7] << 16) | *(uint16_t*)&h[6];
    ul.x = ((uint32_t)*(uint16_t*)&l[1] << 16) | *(uint16_t*)&l[0];
    ul.y = ((uint32_t)*(uint16_t*)&l[3] << 16) | *(uint16_t*)&l[2];
    ul.z = ((uint32_t)*(uint16_t*)&l[5] << 16) | *(uint16_t*)&l[4];
    ul.w = ((uint32_t)*(uint16_t*)&l[7] << 16) | *(uint16_t*)&l[6];
    *dh = uh;
    *dl = ul;
}

// ---------------------------------------------------------------------------
// Pass 2: HMMA grouped GEMM, split-bf16, 3-stage cp.async pipeline (KC=32,
// one __syncthreads per chunk, stage issued AFTER compute so the freed
// buffer is provably drained).
// ---------------------------------------------------------------------------
__device__ __forceinline__ void stage_chunk(uint32_t sdst, int c,
                                            const __nv_bfloat16* Xhi,
                                            const __nv_bfloat16* Xlo,
                                            const __nv_bfloat16* Whi,
                                            const __nv_bfloat16* Wlo,
                                            const int* toks, int tid)
{
    const int k0 = c * KC;
    // A: 128 rows x 32 bf16 -> 512 16B vectors; 2 per thread (x hi+lo)
#pragma unroll
    for (int t = 0; t < 2; t++) {
        int i = tid + t * 256;
        int row = i >> 2;
        int c8 = (i & 3) * 8;
        int tok = toks[row];
        uint32_t nb = (tok >= 0) ? 16u : 0u;   // zero-fill pad rows
        size_t src = (size_t)(tok >= 0 ? tok : 0) * DIM + k0 + c8;
        uint32_t d = sdst + (uint32_t)(A_HI_E + row * LDSA + c8) * 2;
        cp16(d, Xhi + src, nb);
        cp16(d + (uint32_t)(A_LO_E - A_HI_E) * 2, Xlo + src, nb);
    }
    // B: 32 k-rows x 64 bf16 -> 256 16B vectors; 1 per thread (x hi+lo)
    {
        int row = tid >> 3;
        int c8 = (tid & 7) * 8;
        size_t src = (size_t)(k0 + row) * HOUT + c8;
        uint32_t d = sdst + (uint32_t)(B_HI_E + row * LDSB + c8) * 2;
        cp16(d, Whi + src, 16u);
        cp16(d + (uint32_t)(B_LO_E - B_HI_E) * 2, Wlo + src, 16u);
    }
    cp_commit();
}

__global__ __launch_bounds__(256, 2)
void gemm_hmma_kernel(const float* __restrict__ Bv, float* __restrict__ Y)
{
    extern __shared__ __nv_bfloat16 sm[];
    __shared__ int toks[BM];

    const int mt = blockIdx.x;
    const int nt = blockIdx.y;
    const int e  = g_tile_expert[mt];
    if (e < 0) return;

    const int tid = threadIdx.x;
    const int wid = tid >> 5;
    const int lid = tid & 31;
    const int ntb = nt * BN;

    if (tid < BM) toks[tid] = g_order[mt * BM + tid];
    __syncthreads();

    const __nv_bfloat16* Xhi = (const __nv_bfloat16*)g_Xhi4;
    const __nv_bfloat16* Xlo = (const __nv_bfloat16*)g_Xlo4;
    const __nv_bfloat16* Whi = (const __nv_bfloat16*)g_Whi4 + (size_t)e * DIM * HOUT + ntb;
    const __nv_bfloat16* Wlo = (const __nv_bfloat16*)g_Wlo4 + (size_t)e * DIM * HOUT + ntb;

    const int m_base = (wid >> 1) * 32;
    const int n_base = (wid & 1) * 32;

    const uint32_t sbase = smem_u32(sm);
    const uint32_t aAddr = sbase +
        (uint32_t)((m_base + (lid & 15)) * LDSA + ((lid >> 4) << 3)) * 2;
    const uint32_t bAddr = sbase +
        (uint32_t)(B_HI_E + (lid & 15) * LDSB + n_base + ((lid >> 4) << 3)) * 2;

    float acc[2][4][4] = {};

    // prologue: stage chunks 0 and 1
    stage_chunk(sbase + 0 * STG_E * 2, 0, Xhi, Xlo, Whi, Wlo, toks, tid);
    stage_chunk(sbase + 1 * STG_E * 2, 1, Xhi, Xlo, Whi, Wlo, toks, tid);

    int buf = 0;
    for (int c = 0; c < NCHUNK; c++) {
        if (c == NCHUNK - 1) cp_wait<0>(); else cp_wait<1>();
        __syncthreads();

        const uint32_t soff = (uint32_t)(buf * STG_E) * 2;

        // compute chunk c: 2 k-steps of 16
#pragma unroll
        for (int ks = 0; ks < 2; ks++) {
            uint32_t ah[2][4], al[2][4], bh[2][4], bl[2][4];
#pragma unroll
            for (int mi = 0; mi < 2; mi++) {
                uint32_t ad = aAddr + soff + (uint32_t)(mi * 16 * LDSA + ks * 16) * 2;
                ldsm_x4(ah[mi], ad);
                ldsm_x4(al[mi], ad + (uint32_t)A_LO_E * 2);
            }
#pragma unroll
            for (int np = 0; np < 2; np++) {
                uint32_t bd = bAddr + soff + (uint32_t)(ks * 16 * LDSB + np * 16) * 2;
                ldsm_x4_t(bh[np], bd);
                ldsm_x4_t(bl[np], bd + (uint32_t)(B_LO_E - B_HI_E) * 2);
            }
#pragma unroll
            for (int mi = 0; mi < 2; mi++)
#pragma unroll
                for (int ni = 0; ni < 4; ni++) {
                    const int np = ni >> 1, hf = (ni & 1) * 2;
                    mma_bf16(acc[mi][ni], ah[mi], bh[np][hf], bh[np][hf + 1]);
                    mma_bf16(acc[mi][ni], ah[mi], bl[np][hf], bl[np][hf + 1]);
                    mma_bf16(acc[mi][ni], al[mi], bh[np][hf], bh[np][hf + 1]);
                }
        }

        // stage chunk c+2 into the buffer freed by chunk c-1 (safe: the
        // barrier above ordered all warps past compute of c-1)
        if (c + 2 < NCHUNK) {
            int nbuf = buf + 2; if (nbuf >= NSTAGE) nbuf -= NSTAGE;
            stage_chunk(sbase + (uint32_t)(nbuf * STG_E) * 2, c + 2,
                        Xhi, Xlo, Whi, Wlo, toks, tid);
        }
        if (++buf == NSTAGE) buf = 0;
    }

    // epilogue: bias + gathered store
#pragma unroll
    for (int mi = 0; mi < 2; mi++) {
        const int r0 = m_base + mi * 16 + (lid >> 2);
        const int tok0 = toks[r0];
        const int tok1 = toks[r0 + 8];
#pragma unroll
        for (int ni = 0; ni < 4; ni++) {
            const int col = ntb + n_base + ni * 8 + (lid & 3) * 2;
            const float2 b2 = *(const float2*)(Bv + (size_t)e * HOUT + col);
            if (tok0 >= 0) {
                float2 o = {acc[mi][ni][0] + b2.x, acc[mi][ni][1] + b2.y};
                *(float2*)(Y + (size_t)tok0 * HOUT + col) = o;
            }
            if (tok1 >= 0) {
                float2 o = {acc[mi][ni][2] + b2.x, acc[mi][ni][3] + b2.y};
                *(float2*)(Y + (size_t)tok1 * HOUT + col) = o;
            }
        }
    }
}

extern "C" void kernel_launch(void* const* d_in, const int* in_sizes, int n_in,
                              void* d_out, int out_size)
{
    const float* X   = (const float*)d_in[0];   // inputs (2048, 512) f32
    const int*   idx = (const int*)d_in[1];     // idx (2048) i32/i64 autodetect
    const float* W   = (const float*)d_in[2];   // weights (16, 512, 512) f32
    const float* Bv  = (const float*)d_in[3];   // biases (16, 512) f32
    float*       Y   = (float*)d_out;           // out (2048, 512) f32

    cudaFuncSetAttribute(gemm_hmma_kernel,
                         cudaFuncAttributeMaxDynamicSharedMemorySize, SMEM_BYTES);

    prep_kernel<<<CONV_BLOCKS + 1, 256>>>((const float4*)W, (const float4*)X, idx);

    dim3 grid(MAX_TILES, HOUT / BN);
    gemm_hmma_kernel<<<grid, 256, SMEM_BYTES>>>(Bv, Y);
}

// round 11
// speedup vs baseline: 2.0368x; 1.1474x over previous
#include <cuda_runtime.h>
#include <cuda_bf16.h>
#include <stdint.h>

// Problem constants
#define N_TOK   2048
#define DIM     512
#define HOUT    512
#define NEXP    16

// GEMM tiling: CTA 64x64, 4 warps of 32x32
#define BM      64
#define BN      64
#define KC      32
#define NCHUNK  (DIM / KC)   // 16
#define NSTAGE  3            // A-tile cp.async stages
#define MAX_TILES 48         // 2048/64 + 16 worst case
#define PAD_TOK (MAX_TILES * BM)   // 3072

// smem layout (bf16 elems)
#define LDSA    40                          // KC+8 pad
#define LDSB    72                          // BN+8 pad (proven conflict-free)
#define A_ST_E  (2 * BM * LDSA)             // hi+lo per A stage = 5120
#define A_LO_E  (BM * LDSA)                 // 2560 (offset of lo within stage)
#define B0_E    (NSTAGE * A_ST_E)           // 15360
#define B_BUF_E (2 * KC * LDSB)             // hi+lo per B buf = 4608
#define B_LO_E  (KC * LDSB)                 // 2304
#define SMEM_BYTES ((B0_E + 2 * B_BUF_E) * 2)   // 49152

// X split scratch (W is converted on the fly now)
#define XELEMS (N_TOK * DIM)
__device__ uint4 g_Xhi4[XELEMS / 8];
__device__ uint4 g_Xlo4[XELEMS / 8];

__device__ int g_order[PAD_TOK];
__device__ int g_tile_expert[MAX_TILES];

// ---------------------------------------------------------------------------
// PTX helpers (sm_80-era only; tcgen05 is gated off by the sm_103 ptxas target)
// ---------------------------------------------------------------------------
__device__ __forceinline__ uint32_t smem_u32(const void* p) {
    uint32_t a;
    asm("{ .reg .u64 t; cvta.to.shared.u64 t, %1; cvt.u32.u64 %0, t; }"
        : "=r"(a) : "l"(p));
    return a;
}
__device__ __forceinline__ void ldsm_x4(uint32_t* r, uint32_t addr) {
    asm volatile("ldmatrix.sync.aligned.m8n8.x4.shared.b16 {%0,%1,%2,%3}, [%4];"
                 : "=r"(r[0]), "=r"(r[1]), "=r"(r[2]), "=r"(r[3]) : "r"(addr));
}
__device__ __forceinline__ void ldsm_x4_t(uint32_t* r, uint32_t addr) {
    asm volatile("ldmatrix.sync.aligned.m8n8.x4.trans.shared.b16 {%0,%1,%2,%3}, [%4];"
                 : "=r"(r[0]), "=r"(r[1]), "=r"(r[2]), "=r"(r[3]) : "r"(addr));
}
__device__ __forceinline__ void mma_bf16(float* c, const uint32_t* a,
                                         uint32_t b0, uint32_t b1) {
    asm volatile(
        "mma.sync.aligned.m16n8k16.row.col.f32.bf16.bf16.f32 "
        "{%0,%1,%2,%3}, {%4,%5,%6,%7}, {%8,%9}, {%0,%1,%2,%3};"
        : "+f"(c[0]), "+f"(c[1]), "+f"(c[2]), "+f"(c[3])
        : "r"(a[0]), "r"(a[1]), "r"(a[2]), "r"(a[3]), "r"(b0), "r"(b1));
}
__device__ __forceinline__ void cp16(uint32_t dst, const void* src,
                                     uint32_t src_bytes) {
    asm volatile("cp.async.cg.shared.global [%0], [%1], 16, %2;"
                 :: "r"(dst), "l"(src), "r"(src_bytes) : "memory");
}
__device__ __forceinline__ void cp_commit() {
    asm volatile("cp.async.commit_group;" ::: "memory");
}
template <int N>
__device__ __forceinline__ void cp_wait() {
    asm volatile("cp.async.wait_group %0;" :: "n"(N) : "memory");
}

// ---------------------------------------------------------------------------
// Bucketing in smem (proven structure; PAD_TOK now 3072).
// ---------------------------------------------------------------------------
__device__ void bucket_block_fast(const int* __restrict__ idx32)
{
    __shared__ int w[2 * N_TOK];
    __shared__ int ord[PAD_TOK];
    __shared__ int cnt[NEXP], off[NEXP], cur[NEXP];
    __shared__ int odd_or;
    const int t = threadIdx.x;

    if (t == 0) odd_or = 0;
    if (t < NEXP) { cnt[t] = 0; cur[t] = 0; }

    for (int i = t; i < N_TOK; i += 256) w[i] = idx32[i];
    __syncthreads();

    int lor = 0;
    for (int i = t; i < N_TOK / 2; i += 256) lor |= w[2 * i + 1];
    if (lor) atomicOr(&odd_or, 1);
    __syncthreads();

    const int stride = (odd_or == 0) ? 2 : 1;
    if (stride == 2) {
        for (int i = t; i < N_TOK; i += 256) w[N_TOK + i] = idx32[N_TOK + i];
        __syncthreads();
    }

    for (int i = t; i < N_TOK; i += 256)
        atomicAdd(&cnt[w[i * stride] & (NEXP - 1)], 1);
    for (int i = t; i < PAD_TOK; i += 256) ord[i] = -1;
    __syncthreads();

    if (t == 0) {
        int po = 0, tile = 0;
        for (int e = 0; e < NEXP; e++) {
            off[e] = po;
            int ntl = (cnt[e] + BM - 1) / BM;
            for (int k = 0; k < ntl; k++) g_tile_expert[tile++] = e;
            po += ntl * BM;
        }
        for (; tile < MAX_TILES; tile++) g_tile_expert[tile] = -1;
    }
    __syncthreads();

    for (int i = t; i < N_TOK; i += 256) {
        int e = w[i * stride] & (NEXP - 1);
        ord[off[e] + atomicAdd(&cur[e], 1)] = i;
    }
    __syncthreads();

    for (int i = t; i < PAD_TOK; i += 256) g_order[i] = ord[i];
}

// ---------------------------------------------------------------------------
// Pass 1: block 0 buckets; blocks [1, XCONV] split X into bf16 hi/lo.
// (W conversion moved into the GEMM — saves a 33MB DRAM round trip.)
// ---------------------------------------------------------------------------
#define XCONV (XELEMS / 8 / 256)   // 512

__global__ void prep_kernel(const float4* __restrict__ X,
                            const int* __restrict__ idx32)
{
    if (blockIdx.x == 0) {
        bucket_block_fast(idx32);
        return;
    }
    const int j = (blockIdx.x - 1) * 256 + threadIdx.x;
    float4 v0 = X[2 * j];
    float4 v1 = X[2 * j + 1];
    float f[8] = {v0.x, v0.y, v0.z, v0.w, v1.x, v1.y, v1.z, v1.w};
    __nv_bfloat16 h[8], l[8];
#pragma unroll
    for (int q = 0; q < 8; q++) {
        h[q] = __float2bfloat16(f[q]);
        l[q] = __float2bfloat16(f[q] - __bfloat162float(h[q]));
    }
    uint4 uh, ul;
    uh.x = ((uint32_t)*(uint16_t*)&h[1] << 16) | *(uint16_t*)&h[0];
    uh.y = ((uint32_t)*(uint16_t*)&h[3] << 16) | *(uint16_t*)&h[2];
    uh.z = ((uint32_t)*(uint16_t*)&h[5] << 16) | *(uint16_t*)&h[4];
    uh.w = ((uint32_t)*(uint16_t*)&h[7] << 16) | *(uint16_t*)&h[6];
    ul.x = ((uint32_t)*(uint16_t*)&l[1] << 16) | *(uint16_t*)&l[0];
    ul.y = ((uint32_t)*(uint16_t*)&l[3] << 16) | *(uint16_t*)&l[2];
    ul.z = ((uint32_t)*(uint16_t*)&l[5] << 16) | *(uint16_t*)&l[4];
    ul.w = ((uint32_t)*(uint16_t*)&l[7] << 16) | *(uint16_t*)&l[6];
    g_Xhi4[j] = uh;
    g_Xlo4[j] = ul;
}

// ---------------------------------------------------------------------------
// Pass 2: HMMA grouped GEMM. A (X hi/lo) via 3-stage cp.async; W loaded as
// fp32 into registers one chunk ahead, split to bf16 hi/lo, STS into a
// double-buffered B tile. One __syncthreads per chunk.
// ---------------------------------------------------------------------------
__device__ __forceinline__ void stage_a(uint32_t sdst, int c,
                                        const __nv_bfloat16* Xhi,
                                        const __nv_bfloat16* Xlo,
                                        const int* toks, int tid)
{
    const int k0 = c * KC;
#pragma unroll
    for (int t = 0; t < 2; t++) {
        int i = tid + t * 128;          // 0..255: 64 rows x 4 vecs
        int row = i >> 2;
        int c8 = (i & 3) * 8;
        int tok = toks[row];
        uint32_t nb = (tok >= 0) ? 16u : 0u;
        size_t src = (size_t)(tok >= 0 ? tok : 0) * DIM + k0 + c8;
        uint32_t d = sdst + (uint32_t)(row * LDSA + c8) * 2;
        cp16(d, Xhi + src, nb);
        cp16(d + (uint32_t)A_LO_E * 2, Xlo + src, nb);
    }
    cp_commit();
}

__device__ __forceinline__ void ldg_b(float4* r, const float* Wf, int c, int tid)
{
    const int k0 = c * KC;
#pragma unroll
    for (int t = 0; t < 4; t++) {
        int i = tid + t * 128;          // 0..511: 32 rows x 16 vecs
        int row = i >> 4;
        int c4 = (i & 15) * 4;
        r[t] = *(const float4*)(Wf + (size_t)(k0 + row) * HOUT + c4);
    }
}

__device__ __forceinline__ void sts_b(uint32_t sbase, int bufsel,
                                      const float4* r, int tid)
{
    const uint32_t base = sbase + (uint32_t)(B0_E + bufsel * B_BUF_E) * 2;
#pragma unroll
    for (int t = 0; t < 4; t++) {
        int i = tid + t * 128;
        int row = i >> 4;
        int c4 = (i & 15) * 4;
        float f[4] = {r[t].x, r[t].y, r[t].z, r[t].w};
        __nv_bfloat16 h[4], l[4];
#pragma unroll
        for (int q = 0; q < 4; q++) {
            h[q] = __float2bfloat16(f[q]);
            l[q] = __float2bfloat16(f[q] - __bfloat162float(h[q]));
        }
        uint32_t uh0 = ((uint32_t)*(uint16_t*)&h[1] << 16) | *(uint16_t*)&h[0];
        uint32_t uh1 = ((uint32_t)*(uint16_t*)&h[3] << 16) | *(uint16_t*)&h[2];
        uint32_t ul0 = ((uint32_t)*(uint16_t*)&l[1] << 16) | *(uint16_t*)&l[0];
        uint32_t ul1 = ((uint32_t)*(uint16_t*)&l[3] << 16) | *(uint16_t*)&l[2];
        uint32_t d = base + (uint32_t)(row * LDSB + c4) * 2;
        asm volatile("st.shared.v2.b32 [%0], {%1, %2};"
                     :: "r"(d), "r"(uh0), "r"(uh1) : "memory");
        asm volatile("st.shared.v2.b32 [%0], {%1, %2};"
                     :: "r"(d + (uint32_t)B_LO_E * 2), "r"(ul0), "r"(ul1)
                     : "memory");
    }
}

__global__ __launch_bounds__(128, 4)
void gemm_hmma_kernel(const float* __restrict__ W,
                      const float* __restrict__ Bv,
                      float* __restrict__ Y)
{
    extern __shared__ __nv_bfloat16 sm[];
    __shared__ int toks[BM];

    const int mt = blockIdx.x;
    const int nt = blockIdx.y;
    const int e  = g_tile_expert[mt];
    if (e < 0) return;

    const int tid = threadIdx.x;
    const int wid = tid >> 5;          // 0..3
    const int lid = tid & 31;
    const int ntb = nt * BN;

    if (tid < BM) toks[tid] = g_order[mt * BM + tid];
    __syncthreads();

    const __nv_bfloat16* Xhi = (const __nv_bfloat16*)g_Xhi4;
    const __nv_bfloat16* Xlo = (const __nv_bfloat16*)g_Xlo4;
    const float* Wf = W + (size_t)e * DIM * HOUT + ntb;

    const int m_base = (wid >> 1) * 32;
    const int n_base = (wid & 1) * 32;

    const uint32_t sbase = smem_u32(sm);
    const uint32_t aAddr = sbase +
        (uint32_t)((m_base + (lid & 15)) * LDSA + ((lid >> 4) << 3)) * 2;
    const uint32_t bAddr = sbase +
        (uint32_t)(B0_E + (lid & 15) * LDSB + n_base + ((lid >> 4) << 3)) * 2;

    float acc[2][4][4] = {};
    float4 breg[4];

    // prologue
    stage_a(sbase + 0 * A_ST_E * 2, 0, Xhi, Xlo, toks, tid);
    stage_a(sbase + 1 * A_ST_E * 2, 1, Xhi, Xlo, toks, tid);
    ldg_b(breg, Wf, 0, tid);
    sts_b(sbase, 0, breg, tid);
    ldg_b(breg, Wf, 1, tid);

    int abuf = 0;
    for (int c = 0; c < NCHUNK; c++) {
        if (c == NCHUNK - 1) cp_wait<0>(); else cp_wait<1>();
        __syncthreads();
        // All warps are past compute(c-1): safe to fill B buf (c+1)&1 (the
        // buffer compute(c-1) read) and to read A stage c / B buf c&1.

        if (c + 1 < NCHUNK) sts_b(sbase, (c + 1) & 1, breg, tid);

        const uint32_t aoff = (uint32_t)(abuf * A_ST_E) * 2;
        const uint32_t boff = (uint32_t)((c & 1) * B_BUF_E) * 2;

#pragma unroll
        for (int ks = 0; ks < 2; ks++) {
            uint32_t ah[2][4], al[2][4], bh[2][4], bl[2][4];
#pragma unroll
            for (int mi = 0; mi < 2; mi++) {
                uint32_t ad = aAddr + aoff + (uint32_t)(mi * 16 * LDSA + ks * 16) * 2;
                ldsm_x4(ah[mi], ad);
                ldsm_x4(al[mi], ad + (uint32_t)A_LO_E * 2);
            }
#pragma unroll
            for (int np = 0; np < 2; np++) {
                uint32_t bd = bAddr + boff + (uint32_t)(ks * 16 * LDSB + np * 16) * 2;
                ldsm_x4_t(bh[np], bd);
                ldsm_x4_t(bl[np], bd + (uint32_t)B_LO_E * 2);
            }
#pragma unroll
            for (int mi = 0; mi < 2; mi++)
#pragma unroll
                for (int ni = 0; ni < 4; ni++) {
                    const int np = ni >> 1, hf = (ni & 1) * 2;
                    mma_bf16(acc[mi][ni], ah[mi], bh[np][hf], bh[np][hf + 1]);
                    mma_bf16(acc[mi][ni], ah[mi], bl[np][hf], bl[np][hf + 1]);
                    mma_bf16(acc[mi][ni], al[mi], bh[np][hf], bh[np][hf + 1]);
                }
        }

        if (c + 2 < NCHUNK) {
            ldg_b(breg, Wf, c + 2, tid);
            int nbuf = abuf + 2; if (nbuf >= NSTAGE) nbuf -= NSTAGE;
            stage_a(sbase + (uint32_t)(nbuf * A_ST_E) * 2, c + 2, Xhi, Xlo, toks, tid);
        }
        if (++abuf == NSTAGE) abuf = 0;
    }

    // epilogue: bias + gathered store
#pragma unroll
    for (int mi = 0; mi < 2; mi++) {
        const int r0 = m_base + mi * 16 + (lid >> 2);
        const int tok0 = toks[r0];
        const int tok1 = toks[r0 + 8];
#pragma unroll
        for (int ni = 0; ni < 4; ni++) {
            const int col = ntb + n_base + ni * 8 + (lid & 3) * 2;
            const float2 b2 = *(const float2*)(Bv + (size_t)e * HOUT + col);
            if (tok0 >= 0) {
                float2 o = {acc[mi][ni][0] + b2.x, acc[mi][ni][1] + b2.y};
                *(float2*)(Y + (size_t)tok0 * HOUT + col) = o;
            }
            if (tok1 >= 0) {
                float2 o = {acc[mi][ni][2] + b2.x, acc[mi][ni][3] + b2.y};
                *(float2*)(Y + (size_t)tok1 * HOUT + col) = o;
            }
        }
    }
}

extern "C" void kernel_launch(void* const* d_in, const int* in_sizes, int n_in,
                              void* d_out, int out_size)
{
    const float* X   = (const float*)d_in[0];   // inputs (2048, 512) f32
    const int*   idx = (const int*)d_in[1];     // idx (2048) i32/i64 autodetect
    const float* W   = (const float*)d_in[2];   // weights (16, 512, 512) f32
    const float* Bv  = (const float*)d_in[3];   // biases (16, 512) f32
    float*       Y   = (float*)d_out;           // out (2048, 512) f32

    cudaFuncSetAttribute(gemm_hmma_kernel,
                         cudaFuncAttributeMaxDynamicSharedMemorySize, SMEM_BYTES);

    prep_kernel<<<XCONV + 1, 256>>>((const float4*)X, idx);

    dim3 grid(MAX_TILES, HOUT / BN);
    gemm_hmma_kernel<<<grid, 128, SMEM_BYTES>>>(W, Bv, Y);
}